// round 12
// baseline (speedup 1.0000x reference)
#include <cuda_runtime.h>
#include <cuda_fp16.h>
#include <math.h>
#include <stdint.h>

#define TOKENS  16384
#define D_IN    2048
#define D_HID   1024
#define NEXP    64
#define TOPK    8

// ---------------------------------------------------------------------------
// Scratch (__device__ globals: allowed)
// ---------------------------------------------------------------------------
__device__ float  g_h[(size_t)TOKENS * D_HID];        // 64 MiB
__device__ __half g_xh[(size_t)TOKENS * D_IN];        // fp16 high part
__device__ __half g_xl[(size_t)TOKENS * D_IN];        // fp16 residual * 2048
__device__ __half g_wh[(size_t)D_HID * D_IN];
__device__ __half g_wl[(size_t)D_HID * D_IN];
__device__ int    g_risk_count;
__device__ int    g_risk_list[TOKENS];

// ---------------------------------------------------------------------------
// Helpers
// ---------------------------------------------------------------------------
__device__ __forceinline__ uint32_t smem_to_u32(const void* smem_ptr) {
    uint32_t addr;
    asm("{ .reg .u64 tmp; cvta.to.shared.u64 tmp, %1; cvt.u32.u64 %0, tmp; }"
        : "=r"(addr) : "l"(smem_ptr));
    return addr;
}

__device__ __forceinline__ void cp16(uint32_t s, const void* g) {
    asm volatile("cp.async.cg.shared.global [%0], [%1], 16;" :: "r"(s), "l"(g));
}
#define CP_COMMIT()  asm volatile("cp.async.commit_group;" ::: "memory")
#define CP_WAIT2()   asm volatile("cp.async.wait_group 2;" ::: "memory")
#define CP_WAIT1()   asm volatile("cp.async.wait_group 1;" ::: "memory")
#define CP_WAIT0()   asm volatile("cp.async.wait_group 0;" ::: "memory")

__device__ __forceinline__ void ldsm_x4(uint32_t* r, uint32_t addr) {
    asm volatile("ldmatrix.sync.aligned.m8n8.x4.shared.b16 {%0,%1,%2,%3}, [%4];"
        : "=r"(r[0]), "=r"(r[1]), "=r"(r[2]), "=r"(r[3]) : "r"(addr));
}
__device__ __forceinline__ void ldsm_x2(uint32_t* r, uint32_t addr) {
    asm volatile("ldmatrix.sync.aligned.m8n8.x2.shared.b16 {%0,%1}, [%2];"
        : "=r"(r[0]), "=r"(r[1]) : "r"(addr));
}

__device__ __forceinline__ void mma16816(float* c, const uint32_t* a, const uint32_t* b) {
    asm volatile(
        "mma.sync.aligned.m16n8k16.row.col.f32.f16.f16.f32 "
        "{%0,%1,%2,%3}, {%4,%5,%6,%7}, {%8,%9}, {%0,%1,%2,%3};"
        : "+f"(c[0]), "+f"(c[1]), "+f"(c[2]), "+f"(c[3])
        : "r"(a[0]), "r"(a[1]), "r"(a[2]), "r"(a[3]), "r"(b[0]), "r"(b[1]));
}

__device__ __forceinline__ uint32_t sw128(uint32_t off) {
    return off ^ ((off >> 3) & 0x70);
}

// ---------------------------------------------------------------------------
// Kernel Z: reset at-risk counter
// ---------------------------------------------------------------------------
__global__ void zero_kernel() { g_risk_count = 0; }

// ---------------------------------------------------------------------------
// Kernel S: fp16 2-way split. a = h + l/2048, l stored pre-scaled by 2048.
// ---------------------------------------------------------------------------
__global__ void split_kernel(const float* __restrict__ src, int n4, int which)
{
    __half *dh, *dl;
    if (which == 0) { dh = g_xh; dl = g_xl; }
    else            { dh = g_wh; dl = g_wl; }

    int i = blockIdx.x * blockDim.x + threadIdx.x;
    const int stride = gridDim.x * blockDim.x;
    for (; i < n4; i += stride) {
        float4 v = ((const float4*)src)[i];
        float a[4] = {v.x, v.y, v.z, v.w};
        __half h[4], l[4];
#pragma unroll
        for (int j = 0; j < 4; j++) {
            h[j] = __float2half(a[j]);
            float r = (a[j] - __half2float(h[j])) * 2048.0f;
            l[j] = __float2half(r);
        }
        __half2* ph = (__half2*)dh;
        __half2* pl = (__half2*)dl;
        ph[2*i]   = __half2(h[0], h[1]);
        ph[2*i+1] = __half2(h[2], h[3]);
        pl[2*i]   = __half2(l[0], l[1]);
        pl[2*i+1] = __half2(l[2], l[3]);
    }
}

// ---------------------------------------------------------------------------
// Kernel G: h = leaky(x @ W1^T + b1), mma.sync fp16 split GEMM (3 products)
// CTA 128x128, BK=64, 3-stage cp.async pipeline, 8 warps (2m x 4n),
// ks-outer with fragment reuse. (Structure from R9 — compiled & ran.)
// ---------------------------------------------------------------------------
#define GM 128
#define GN 128
#define GK 64
#define NCHUNK (D_IN / GK)          // 32
#define TILE_B 16384                // 128 rows x 128 bytes (SW128)
#define NSTAGE 3
#define STAGE_B (4 * TILE_B)        // Ah Al Bh Bl = 64 KB
#define SMEM_CTRL 1024
#define SMEM_TOTAL_G (SMEM_CTRL + NSTAGE * STAGE_B)   // 197632

__global__ __launch_bounds__(256, 1)
void gemm1_mma_kernel(const float* __restrict__ b1)
{
    extern __shared__ char smem[];
    const uint32_t sb = smem_to_u32(smem);
    const int tid  = threadIdx.x;
    const int wid  = tid >> 5;
    const int lane = tid & 31;
    const int m0 = blockIdx.y * GM;
    const int n0 = blockIdx.x * GN;

    const int wm0 = (wid & 1) * 64;
    const int wn0 = (wid >> 1) * 32;

    size_t   goff[4];
    uint32_t soff[4];
#pragma unroll
    for (int p = 0; p < 4; p++) {
        int u = tid + p * 256;
        int row = u >> 3, c16 = u & 7;
        goff[p] = (size_t)row * D_IN + c16 * 8;
        soff[p] = sw128(row * 128 + c16 * 16);
    }

    const __half* Ab[2] = { g_xh + (size_t)m0 * D_IN, g_xl + (size_t)m0 * D_IN };
    const __half* Bb[2] = { g_wh + (size_t)n0 * D_IN, g_wl + (size_t)n0 * D_IN };

    auto load_chunk = [&](int chunk, int buf) {
        const int kt = chunk * GK;
        const uint32_t stg = sb + SMEM_CTRL + buf * STAGE_B;
#pragma unroll
        for (int t = 0; t < 4; t++) {
            const __half* base = (t < 2) ? Ab[t] : Bb[t - 2];
            const uint32_t sbase = stg + t * TILE_B;
#pragma unroll
            for (int p = 0; p < 4; p++)
                cp16(sbase + soff[p], base + goff[p] + kt);
        }
        CP_COMMIT();
    };

    const uint32_t a_row = wm0 + (lane & 15);
    const uint32_t a_kb  = (lane >> 4) * 16;
    const uint32_t b_row = wn0 + (lane & 7);
    const uint32_t b_kb  = ((lane >> 3) & 1) * 16;

    float acc0[4][4][4];
    float acc1[4][4][4];
#pragma unroll
    for (int mi = 0; mi < 4; mi++)
#pragma unroll
        for (int ni = 0; ni < 4; ni++)
#pragma unroll
            for (int e = 0; e < 4; e++) { acc0[mi][ni][e] = 0.0f; acc1[mi][ni][e] = 0.0f; }

    load_chunk(0, 0);
    load_chunk(1, 1);
    load_chunk(2, 2);

    for (int i = 0; i < NCHUNK; i++) {
        if (i + 3 <= NCHUNK)      CP_WAIT2();
        else if (i + 2 <= NCHUNK) CP_WAIT1();
        else                      CP_WAIT0();
        __syncthreads();

        const uint32_t stg = sb + SMEM_CTRL + (i % NSTAGE) * STAGE_B;
        const uint32_t ah = stg;
        const uint32_t al = stg + TILE_B;
        const uint32_t bh = stg + 2 * TILE_B;
        const uint32_t bl = stg + 3 * TILE_B;

#pragma unroll
        for (int ks = 0; ks < 4; ks++) {
            uint32_t afh[4][4], afl[4][4];
#pragma unroll
            for (int mi = 0; mi < 4; mi++) {
                uint32_t off = (a_row + mi * 16) * 128 + ks * 32 + a_kb;
                uint32_t sw  = sw128(off);
                ldsm_x4(afh[mi], ah + sw);
                ldsm_x4(afl[mi], al + sw);
            }
            uint32_t bfh[4][2], bfl[4][2];
#pragma unroll
            for (int ni = 0; ni < 4; ni++) {
                uint32_t off = (b_row + ni * 8) * 128 + ks * 32 + b_kb;
                uint32_t sw  = sw128(off);
                ldsm_x2(bfh[ni], bh + sw);
                ldsm_x2(bfl[ni], bl + sw);
            }
#pragma unroll
            for (int mi = 0; mi < 4; mi++)
#pragma unroll
                for (int ni = 0; ni < 4; ni++)
                    mma16816(acc0[mi][ni], afh[mi], bfh[ni]);
#pragma unroll
            for (int mi = 0; mi < 4; mi++)
#pragma unroll
                for (int ni = 0; ni < 4; ni++)
                    mma16816(acc1[mi][ni], afh[mi], bfl[ni]);
#pragma unroll
            for (int mi = 0; mi < 4; mi++)
#pragma unroll
                for (int ni = 0; ni < 4; ni++)
                    mma16816(acc1[mi][ni], afl[mi], bfh[ni]);
        }
        __syncthreads();
        if (i + 3 < NCHUNK) load_chunk(i + 3, (i + 3) % NSTAGE);
    }

    const float CS = 1.0f / 2048.0f;
    float2 bv[4];
#pragma unroll
    for (int ni = 0; ni < 4; ni++) {
        int col = n0 + wn0 + ni * 8 + (lane & 3) * 2;
        bv[ni] = make_float2(b1[col], b1[col + 1]);
    }

#pragma unroll
    for (int mi = 0; mi < 4; mi++) {
        const int r0 = m0 + wm0 + mi * 16 + (lane >> 2);
#pragma unroll
        for (int ni = 0; ni < 4; ni++) {
            const int col = n0 + wn0 + ni * 8 + (lane & 3) * 2;
            float t0 = acc0[mi][ni][0] + CS * acc1[mi][ni][0] + bv[ni].x;
            float t1 = acc0[mi][ni][1] + CS * acc1[mi][ni][1] + bv[ni].y;
            float t2 = acc0[mi][ni][2] + CS * acc1[mi][ni][2] + bv[ni].x;
            float t3 = acc0[mi][ni][3] + CS * acc1[mi][ni][3] + bv[ni].y;
            t0 = (t0 >= 0.f) ? t0 : 0.01f * t0;
            t1 = (t1 >= 0.f) ? t1 : 0.01f * t1;
            t2 = (t2 >= 0.f) ? t2 : 0.01f * t2;
            t3 = (t3 >= 0.f) ? t3 : 0.01f * t3;
            *(float2*)(g_h + (size_t)r0 * D_HID + col)       = make_float2(t0, t1);
            *(float2*)(g_h + (size_t)(r0 + 8) * D_HID + col) = make_float2(t2, t3);
        }
    }
}

// ---------------------------------------------------------------------------
// Kernel R: logits = h @ W2^T + b2 ; top-9 ; softmax over top-8 ;
// flags tokens whose min gap among the top-9 values is < GAP_TAU.
// ---------------------------------------------------------------------------
#define TT 64
#define KC 64
#define LSTR (TT + 4)
#define GAP_TAU 2e-4f

__global__ __launch_bounds__(256, 1)
void router_kernel(const float* __restrict__ W2,
                   const float* __restrict__ b2,
                   float* __restrict__ out,
                   int write_indices)
{
    __shared__ float smem[2 * KC * LSTR];
    float (*Hs)[LSTR] = (float(*)[LSTR])(smem);
    float (*Ws)[LSTR] = (float(*)[LSTR])(smem + KC * LSTR);
    float* Lg = smem;

    const int tid  = threadIdx.x;
    const int t0   = blockIdx.x * TT;

    const int lrow = tid >> 4;        // 0..15
    const int lcol = (tid & 15) * 4;  // 0..60

    const int ty = tid >> 4;   // token octet (tid<128)
    const int tx = tid & 15;   // expert quad

    float acc[8][4];
#pragma unroll
    for (int i = 0; i < 8; i++)
#pragma unroll
        for (int j = 0; j < 4; j++) acc[i][j] = 0.0f;

    for (int kc = 0; kc < D_HID; kc += KC) {
#pragma unroll
        for (int p = 0; p < 4; p++) {
            const int row = lrow + p * 16;
            float4 a = *(const float4*)(g_h + (size_t)(t0 + row) * D_HID + kc + lcol);
            Hs[lcol + 0][row] = a.x;
            Hs[lcol + 1][row] = a.y;
            Hs[lcol + 2][row] = a.z;
            Hs[lcol + 3][row] = a.w;
            float4 b = *(const float4*)(W2 + (size_t)row * D_HID + kc + lcol);
            Ws[lcol + 0][row] = b.x;
            Ws[lcol + 1][row] = b.y;
            Ws[lcol + 2][row] = b.z;
            Ws[lcol + 3][row] = b.w;
        }
        __syncthreads();

        if (tid < 128) {
#pragma unroll 8
            for (int k = 0; k < KC; k++) {
                float af[8], bf[4];
                *(float4*)(af + 0) = *(const float4*)&Hs[k][ty * 8 + 0];
                *(float4*)(af + 4) = *(const float4*)&Hs[k][ty * 8 + 4];
                *(float4*)(bf + 0) = *(const float4*)&Ws[k][tx * 4];
#pragma unroll
                for (int i = 0; i < 8; i++)
#pragma unroll
                    for (int j = 0; j < 4; j++)
                        acc[i][j] = fmaf(af[i], bf[j], acc[i][j]);
            }
        }
        __syncthreads();
    }

    if (tid < 128) {
        float bb[4];
#pragma unroll
        for (int j = 0; j < 4; j++) bb[j] = b2[tx * 4 + j];
#pragma unroll
        for (int i = 0; i < 8; i++) {
            float4 v = make_float4(acc[i][0] + bb[0], acc[i][1] + bb[1],
                                   acc[i][2] + bb[2], acc[i][3] + bb[3]);
            *(float4*)&Lg[(ty * 8 + i) * LSTR + tx * 4] = v;
        }
    }
    __syncthreads();

    const int warp = tid >> 5;
    const int lane = tid & 31;
    const float NEG = -3.402823466e38f;

    for (int s = 0; s < 8; s++) {
        const int lt = warp * 8 + s;
        float v0 = Lg[lt * LSTR + lane];
        float v1 = Lg[lt * LSTR + 32 + lane];
        const int i0 = lane;
        const int i1 = lane + 32;

        float pv[TOPK + 1];
        int   pi[TOPK + 1];
#pragma unroll
        for (int r = 0; r < TOPK + 1; r++) {
            float bv; int bi;
            if (v0 >= v1) { bv = v0; bi = i0; } else { bv = v1; bi = i1; }
#pragma unroll
            for (int off = 16; off >= 1; off >>= 1) {
                float ov = __shfl_xor_sync(0xffffffffu, bv, off);
                int   oi = __shfl_xor_sync(0xffffffffu, bi, off);
                if (ov > bv || (ov == bv && oi < bi)) { bv = ov; bi = oi; }
            }
            pv[r] = bv; pi[r] = bi;
            if (bi == i0)       v0 = NEG;
            else if (bi == i1)  v1 = NEG;
        }

        if (lane == 0) {
            const int gt = t0 + lt;
            const float mx = pv[0];
            float e[TOPK], sum = 0.0f;
#pragma unroll
            for (int r = 0; r < TOPK; r++) { e[r] = expf(pv[r] - mx); sum += e[r]; }
            const float inv = 1.0f / sum;
#pragma unroll
            for (int r = 0; r < TOPK; r++)
                out[(size_t)gt * TOPK + r] = e[r] * inv;
            if (write_indices) {
#pragma unroll
                for (int r = 0; r < TOPK; r++)
                    out[(size_t)TOKENS * TOPK + (size_t)gt * TOPK + r] = (float)pi[r];
            }
            // gap check over all 9 retained values (8 internal + boundary)
            float mingap = 3.402823466e38f;
#pragma unroll
            for (int r = 0; r < TOPK; r++) {
                float gp = pv[r] - pv[r + 1];
                mingap = (gp < mingap) ? gp : mingap;
            }
            if (mingap < GAP_TAU) {
                int slot = atomicAdd(&g_risk_count, 1);
                g_risk_list[slot] = gt;
            }
        }
    }
}

// ---------------------------------------------------------------------------
// Kernel X: rescue. Recompute flagged tokens with ascending-k fp32 FMA
// chains (the semantics that matched the reference at 9e-8 in R2) and
// overwrite their outputs.
// ---------------------------------------------------------------------------
__global__ __launch_bounds__(256, 1)
void rescue_kernel(const float* __restrict__ X,
                   const float* __restrict__ W1,
                   const float* __restrict__ b1,
                   const float* __restrict__ W2,
                   const float* __restrict__ b2,
                   float* __restrict__ out,
                   int write_indices)
{
    __shared__ float hs[D_HID];
    __shared__ float lg[NEXP];

    const int cnt = g_risk_count;
    const int tid = threadIdx.x;

    for (int it = blockIdx.x; it < cnt; it += gridDim.x) {
        const int t = g_risk_list[it];
        const float* xr = X + (size_t)t * D_IN;

        // h[j] = leaky(sum_k x[k]*W1[j,k] + b1[j]), ascending k, single acc
        for (int j = tid; j < D_HID; j += 256) {
            const float* wr = W1 + (size_t)j * D_IN;
            float a = 0.0f;
#pragma unroll 8
            for (int k = 0; k < D_IN; k++)
                a = fmaf(xr[k], wr[k], a);
            a += b1[j];
            hs[j] = (a >= 0.0f) ? a : 0.01f * a;
        }
        __syncthreads();

        // logits[e] = sum_d h[d]*W2[e,d] + b2[e], ascending d
        if (tid < NEXP) {
            const float* w2r = W2 + (size_t)tid * D_HID;
            float a = 0.0f;
#pragma unroll 8
            for (int d = 0; d < D_HID; d++)
                a = fmaf(hs[d], w2r[d], a);
            lg[tid] = a + b2[tid];
        }
        __syncthreads();

        // warp 0: top-8 + softmax, overwrite outputs
        if (tid < 32) {
            const int lane = tid;
            const float NEG = -3.402823466e38f;
            float v0 = lg[lane];
            float v1 = lg[32 + lane];
            const int i0 = lane;
            const int i1 = lane + 32;

            float pv[TOPK];
            int   pi[TOPK];
#pragma unroll
            for (int r = 0; r < TOPK; r++) {
                float bv; int bi;
                if (v0 >= v1) { bv = v0; bi = i0; } else { bv = v1; bi = i1; }
#pragma unroll
                for (int off = 16; off >= 1; off >>= 1) {
                    float ov = __shfl_xor_sync(0xffffffffu, bv, off);
                    int   oi = __shfl_xor_sync(0xffffffffu, bi, off);
                    if (ov > bv || (ov == bv && oi < bi)) { bv = ov; bi = oi; }
                }
                pv[r] = bv; pi[r] = bi;
                if (bi == i0)       v0 = NEG;
                else if (bi == i1)  v1 = NEG;
            }

            if (lane == 0) {
                const float mx = pv[0];
                float e[TOPK], sum = 0.0f;
#pragma unroll
                for (int r = 0; r < TOPK; r++) { e[r] = expf(pv[r] - mx); sum += e[r]; }
                const float inv = 1.0f / sum;
#pragma unroll
                for (int r = 0; r < TOPK; r++)
                    out[(size_t)t * TOPK + r] = e[r] * inv;
                if (write_indices) {
#pragma unroll
                    for (int r = 0; r < TOPK; r++)
                        out[(size_t)TOKENS * TOPK + (size_t)t * TOPK + r] = (float)pi[r];
                }
            }
        }
        __syncthreads();
    }
}

// ---------------------------------------------------------------------------
extern "C" void kernel_launch(void* const* d_in, const int* in_sizes, int n_in,
                              void* d_out, int out_size)
{
    const float* X  = (const float*)d_in[0];
    const float* W1 = (const float*)d_in[1];
    const float* b1 = (const float*)d_in[2];
    const float* W2 = (const float*)d_in[3];
    const float* b2 = (const float*)d_in[4];
    float* out = (float*)d_out;

    const int write_indices = (out_size >= 2 * TOKENS * TOPK) ? 1 : 0;

    cudaFuncSetAttribute(gemm1_mma_kernel,
                         cudaFuncAttributeMaxDynamicSharedMemorySize, SMEM_TOTAL_G);

    zero_kernel<<<1, 1>>>();
    split_kernel<<<4096, 256>>>(X,  (TOKENS * D_IN) / 4, 0);
    split_kernel<<<2048, 256>>>(W1, (D_HID * D_IN) / 4, 1);

    dim3 gg(D_HID / GN, TOKENS / GM);
    gemm1_mma_kernel<<<gg, 256, SMEM_TOTAL_G>>>(b1);

    router_kernel<<<TOKENS / TT, 256>>>(W2, b2, out, write_indices);

    rescue_kernel<<<128, 256>>>(X, W1, b1, W2, b2, out, write_indices);
}

// round 13
// speedup vs baseline: 2.5125x; 2.5125x over previous
#include <cuda_runtime.h>
#include <cuda_fp16.h>
#include <math.h>
#include <stdint.h>

#define TOKENS  16384
#define D_IN    2048
#define D_HID   1024
#define NEXP    64
#define TOPK    8

// ---------------------------------------------------------------------------
// Scratch (__device__ globals: allowed)
// ---------------------------------------------------------------------------
__device__ float  g_h[(size_t)TOKENS * D_HID];        // 64 MiB
__device__ __half g_xh[(size_t)TOKENS * D_IN];        // fp16 high part
__device__ __half g_xl[(size_t)TOKENS * D_IN];        // fp16 residual * 2048
__device__ __half g_wh[(size_t)D_HID * D_IN];
__device__ __half g_wl[(size_t)D_HID * D_IN];
__device__ int    g_risk_count;
__device__ int    g_risk_list[TOKENS];

// ---------------------------------------------------------------------------
// Helpers
// ---------------------------------------------------------------------------
__device__ __forceinline__ uint32_t smem_to_u32(const void* smem_ptr) {
    uint32_t addr;
    asm("{ .reg .u64 tmp; cvta.to.shared.u64 tmp, %1; cvt.u32.u64 %0, tmp; }"
        : "=r"(addr) : "l"(smem_ptr));
    return addr;
}

__device__ __forceinline__ void cp16(uint32_t s, const void* g) {
    asm volatile("cp.async.cg.shared.global [%0], [%1], 16;" :: "r"(s), "l"(g));
}
#define CP_COMMIT()  asm volatile("cp.async.commit_group;" ::: "memory")
#define CP_WAIT2()   asm volatile("cp.async.wait_group 2;" ::: "memory")
#define CP_WAIT1()   asm volatile("cp.async.wait_group 1;" ::: "memory")
#define CP_WAIT0()   asm volatile("cp.async.wait_group 0;" ::: "memory")

__device__ __forceinline__ void ldsm_x4(uint32_t* r, uint32_t addr) {
    asm volatile("ldmatrix.sync.aligned.m8n8.x4.shared.b16 {%0,%1,%2,%3}, [%4];"
        : "=r"(r[0]), "=r"(r[1]), "=r"(r[2]), "=r"(r[3]) : "r"(addr));
}
__device__ __forceinline__ void ldsm_x2(uint32_t* r, uint32_t addr) {
    asm volatile("ldmatrix.sync.aligned.m8n8.x2.shared.b16 {%0,%1}, [%2];"
        : "=r"(r[0]), "=r"(r[1]) : "r"(addr));
}

__device__ __forceinline__ void mma16816(float* c, const uint32_t* a, const uint32_t* b) {
    asm volatile(
        "mma.sync.aligned.m16n8k16.row.col.f32.f16.f16.f32 "
        "{%0,%1,%2,%3}, {%4,%5,%6,%7}, {%8,%9}, {%0,%1,%2,%3};"
        : "+f"(c[0]), "+f"(c[1]), "+f"(c[2]), "+f"(c[3])
        : "r"(a[0]), "r"(a[1]), "r"(a[2]), "r"(a[3]), "r"(b[0]), "r"(b[1]));
}

__device__ __forceinline__ uint32_t sw128(uint32_t off) {
    return off ^ ((off >> 3) & 0x70);
}

// ---------------------------------------------------------------------------
// Kernel Z: reset at-risk counter
// ---------------------------------------------------------------------------
__global__ void zero_kernel() { g_risk_count = 0; }

// ---------------------------------------------------------------------------
// Kernel S: fp16 2-way split. a = h + l/2048, l stored pre-scaled by 2048.
// ---------------------------------------------------------------------------
__global__ void split_kernel(const float* __restrict__ src, int n4, int which)
{
    __half *dh, *dl;
    if (which == 0) { dh = g_xh; dl = g_xl; }
    else            { dh = g_wh; dl = g_wl; }

    int i = blockIdx.x * blockDim.x + threadIdx.x;
    const int stride = gridDim.x * blockDim.x;
    for (; i < n4; i += stride) {
        float4 v = ((const float4*)src)[i];
        float a[4] = {v.x, v.y, v.z, v.w};
        __half h[4], l[4];
#pragma unroll
        for (int j = 0; j < 4; j++) {
            h[j] = __float2half(a[j]);
            float r = (a[j] - __half2float(h[j])) * 2048.0f;
            l[j] = __float2half(r);
        }
        __half2* ph = (__half2*)dh;
        __half2* pl = (__half2*)dl;
        ph[2*i]   = __half2(h[0], h[1]);
        ph[2*i+1] = __half2(h[2], h[3]);
        pl[2*i]   = __half2(l[0], l[1]);
        pl[2*i+1] = __half2(l[2], l[3]);
    }
}

// ---------------------------------------------------------------------------
// Kernel G: h = leaky(x @ W1^T + b1), mma.sync fp16 split GEMM (3 products)
// (byte-identical to R12 — known 461us, known-safe flag interplay)
// ---------------------------------------------------------------------------
#define GM 128
#define GN 128
#define GK 64
#define NCHUNK (D_IN / GK)          // 32
#define TILE_B 16384                // 128 rows x 128 bytes (SW128)
#define NSTAGE 3
#define STAGE_B (4 * TILE_B)        // Ah Al Bh Bl = 64 KB
#define SMEM_CTRL 1024
#define SMEM_TOTAL_G (SMEM_CTRL + NSTAGE * STAGE_B)   // 197632

__global__ __launch_bounds__(256, 1)
void gemm1_mma_kernel(const float* __restrict__ b1)
{
    extern __shared__ char smem[];
    const uint32_t sb = smem_to_u32(smem);
    const int tid  = threadIdx.x;
    const int wid  = tid >> 5;
    const int lane = tid & 31;
    const int m0 = blockIdx.y * GM;
    const int n0 = blockIdx.x * GN;

    const int wm0 = (wid & 1) * 64;
    const int wn0 = (wid >> 1) * 32;

    size_t   goff[4];
    uint32_t soff[4];
#pragma unroll
    for (int p = 0; p < 4; p++) {
        int u = tid + p * 256;
        int row = u >> 3, c16 = u & 7;
        goff[p] = (size_t)row * D_IN + c16 * 8;
        soff[p] = sw128(row * 128 + c16 * 16);
    }

    const __half* Ab[2] = { g_xh + (size_t)m0 * D_IN, g_xl + (size_t)m0 * D_IN };
    const __half* Bb[2] = { g_wh + (size_t)n0 * D_IN, g_wl + (size_t)n0 * D_IN };

    auto load_chunk = [&](int chunk, int buf) {
        const int kt = chunk * GK;
        const uint32_t stg = sb + SMEM_CTRL + buf * STAGE_B;
#pragma unroll
        for (int t = 0; t < 4; t++) {
            const __half* base = (t < 2) ? Ab[t] : Bb[t - 2];
            const uint32_t sbase = stg + t * TILE_B;
#pragma unroll
            for (int p = 0; p < 4; p++)
                cp16(sbase + soff[p], base + goff[p] + kt);
        }
        CP_COMMIT();
    };

    const uint32_t a_row = wm0 + (lane & 15);
    const uint32_t a_kb  = (lane >> 4) * 16;
    const uint32_t b_row = wn0 + (lane & 7);
    const uint32_t b_kb  = ((lane >> 3) & 1) * 16;

    float acc0[4][4][4];
    float acc1[4][4][4];
#pragma unroll
    for (int mi = 0; mi < 4; mi++)
#pragma unroll
        for (int ni = 0; ni < 4; ni++)
#pragma unroll
            for (int e = 0; e < 4; e++) { acc0[mi][ni][e] = 0.0f; acc1[mi][ni][e] = 0.0f; }

    load_chunk(0, 0);
    load_chunk(1, 1);
    load_chunk(2, 2);

    for (int i = 0; i < NCHUNK; i++) {
        if (i + 3 <= NCHUNK)      CP_WAIT2();
        else if (i + 2 <= NCHUNK) CP_WAIT1();
        else                      CP_WAIT0();
        __syncthreads();

        const uint32_t stg = sb + SMEM_CTRL + (i % NSTAGE) * STAGE_B;
        const uint32_t ah = stg;
        const uint32_t al = stg + TILE_B;
        const uint32_t bh = stg + 2 * TILE_B;
        const uint32_t bl = stg + 3 * TILE_B;

#pragma unroll
        for (int ks = 0; ks < 4; ks++) {
            uint32_t afh[4][4], afl[4][4];
#pragma unroll
            for (int mi = 0; mi < 4; mi++) {
                uint32_t off = (a_row + mi * 16) * 128 + ks * 32 + a_kb;
                uint32_t sw  = sw128(off);
                ldsm_x4(afh[mi], ah + sw);
                ldsm_x4(afl[mi], al + sw);
            }
            uint32_t bfh[4][2], bfl[4][2];
#pragma unroll
            for (int ni = 0; ni < 4; ni++) {
                uint32_t off = (b_row + ni * 8) * 128 + ks * 32 + b_kb;
                uint32_t sw  = sw128(off);
                ldsm_x2(bfh[ni], bh + sw);
                ldsm_x2(bfl[ni], bl + sw);
            }
#pragma unroll
            for (int mi = 0; mi < 4; mi++)
#pragma unroll
                for (int ni = 0; ni < 4; ni++)
                    mma16816(acc0[mi][ni], afh[mi], bfh[ni]);
#pragma unroll
            for (int mi = 0; mi < 4; mi++)
#pragma unroll
                for (int ni = 0; ni < 4; ni++)
                    mma16816(acc1[mi][ni], afh[mi], bfl[ni]);
#pragma unroll
            for (int mi = 0; mi < 4; mi++)
#pragma unroll
                for (int ni = 0; ni < 4; ni++)
                    mma16816(acc1[mi][ni], afl[mi], bfh[ni]);
        }
        __syncthreads();
        if (i + 3 < NCHUNK) load_chunk(i + 3, (i + 3) % NSTAGE);
    }

    const float CS = 1.0f / 2048.0f;
    float2 bv[4];
#pragma unroll
    for (int ni = 0; ni < 4; ni++) {
        int col = n0 + wn0 + ni * 8 + (lane & 3) * 2;
        bv[ni] = make_float2(b1[col], b1[col + 1]);
    }

#pragma unroll
    for (int mi = 0; mi < 4; mi++) {
        const int r0 = m0 + wm0 + mi * 16 + (lane >> 2);
#pragma unroll
        for (int ni = 0; ni < 4; ni++) {
            const int col = n0 + wn0 + ni * 8 + (lane & 3) * 2;
            float t0 = acc0[mi][ni][0] + CS * acc1[mi][ni][0] + bv[ni].x;
            float t1 = acc0[mi][ni][1] + CS * acc1[mi][ni][1] + bv[ni].y;
            float t2 = acc0[mi][ni][2] + CS * acc1[mi][ni][2] + bv[ni].x;
            float t3 = acc0[mi][ni][3] + CS * acc1[mi][ni][3] + bv[ni].y;
            t0 = (t0 >= 0.f) ? t0 : 0.01f * t0;
            t1 = (t1 >= 0.f) ? t1 : 0.01f * t1;
            t2 = (t2 >= 0.f) ? t2 : 0.01f * t2;
            t3 = (t3 >= 0.f) ? t3 : 0.01f * t3;
            *(float2*)(g_h + (size_t)r0 * D_HID + col)       = make_float2(t0, t1);
            *(float2*)(g_h + (size_t)(r0 + 8) * D_HID + col) = make_float2(t2, t3);
        }
    }
}

// ---------------------------------------------------------------------------
// Kernel R: logits = h @ W2^T + b2 ; top-9 ; softmax over top-8 ;
// flags tokens whose min gap among the top-9 values is < GAP_TAU.
// (byte-identical to R12)
// ---------------------------------------------------------------------------
#define TT 64
#define KC 64
#define LSTR (TT + 4)
#define GAP_TAU 2e-4f

__global__ __launch_bounds__(256, 1)
void router_kernel(const float* __restrict__ W2,
                   const float* __restrict__ b2,
                   float* __restrict__ out,
                   int write_indices)
{
    __shared__ float smem[2 * KC * LSTR];
    float (*Hs)[LSTR] = (float(*)[LSTR])(smem);
    float (*Ws)[LSTR] = (float(*)[LSTR])(smem + KC * LSTR);
    float* Lg = smem;

    const int tid  = threadIdx.x;
    const int t0   = blockIdx.x * TT;

    const int lrow = tid >> 4;        // 0..15
    const int lcol = (tid & 15) * 4;  // 0..60

    const int ty = tid >> 4;   // token octet (tid<128)
    const int tx = tid & 15;   // expert quad

    float acc[8][4];
#pragma unroll
    for (int i = 0; i < 8; i++)
#pragma unroll
        for (int j = 0; j < 4; j++) acc[i][j] = 0.0f;

    for (int kc = 0; kc < D_HID; kc += KC) {
#pragma unroll
        for (int p = 0; p < 4; p++) {
            const int row = lrow + p * 16;
            float4 a = *(const float4*)(g_h + (size_t)(t0 + row) * D_HID + kc + lcol);
            Hs[lcol + 0][row] = a.x;
            Hs[lcol + 1][row] = a.y;
            Hs[lcol + 2][row] = a.z;
            Hs[lcol + 3][row] = a.w;
            float4 b = *(const float4*)(W2 + (size_t)row * D_HID + kc + lcol);
            Ws[lcol + 0][row] = b.x;
            Ws[lcol + 1][row] = b.y;
            Ws[lcol + 2][row] = b.z;
            Ws[lcol + 3][row] = b.w;
        }
        __syncthreads();

        if (tid < 128) {
#pragma unroll 8
            for (int k = 0; k < KC; k++) {
                float af[8], bf[4];
                *(float4*)(af + 0) = *(const float4*)&Hs[k][ty * 8 + 0];
                *(float4*)(af + 4) = *(const float4*)&Hs[k][ty * 8 + 4];
                *(float4*)(bf + 0) = *(const float4*)&Ws[k][tx * 4];
#pragma unroll
                for (int i = 0; i < 8; i++)
#pragma unroll
                    for (int j = 0; j < 4; j++)
                        acc[i][j] = fmaf(af[i], bf[j], acc[i][j]);
            }
        }
        __syncthreads();
    }

    if (tid < 128) {
        float bb[4];
#pragma unroll
        for (int j = 0; j < 4; j++) bb[j] = b2[tx * 4 + j];
#pragma unroll
        for (int i = 0; i < 8; i++) {
            float4 v = make_float4(acc[i][0] + bb[0], acc[i][1] + bb[1],
                                   acc[i][2] + bb[2], acc[i][3] + bb[3]);
            *(float4*)&Lg[(ty * 8 + i) * LSTR + tx * 4] = v;
        }
    }
    __syncthreads();

    const int warp = tid >> 5;
    const int lane = tid & 31;
    const float NEG = -3.402823466e38f;

    for (int s = 0; s < 8; s++) {
        const int lt = warp * 8 + s;
        float v0 = Lg[lt * LSTR + lane];
        float v1 = Lg[lt * LSTR + 32 + lane];
        const int i0 = lane;
        const int i1 = lane + 32;

        float pv[TOPK + 1];
        int   pi[TOPK + 1];
#pragma unroll
        for (int r = 0; r < TOPK + 1; r++) {
            float bv; int bi;
            if (v0 >= v1) { bv = v0; bi = i0; } else { bv = v1; bi = i1; }
#pragma unroll
            for (int off = 16; off >= 1; off >>= 1) {
                float ov = __shfl_xor_sync(0xffffffffu, bv, off);
                int   oi = __shfl_xor_sync(0xffffffffu, bi, off);
                if (ov > bv || (ov == bv && oi < bi)) { bv = ov; bi = oi; }
            }
            pv[r] = bv; pi[r] = bi;
            if (bi == i0)       v0 = NEG;
            else if (bi == i1)  v1 = NEG;
        }

        if (lane == 0) {
            const int gt = t0 + lt;
            const float mx = pv[0];
            float e[TOPK], sum = 0.0f;
#pragma unroll
            for (int r = 0; r < TOPK; r++) { e[r] = expf(pv[r] - mx); sum += e[r]; }
            const float inv = 1.0f / sum;
#pragma unroll
            for (int r = 0; r < TOPK; r++)
                out[(size_t)gt * TOPK + r] = e[r] * inv;
            if (write_indices) {
#pragma unroll
                for (int r = 0; r < TOPK; r++)
                    out[(size_t)TOKENS * TOPK + (size_t)gt * TOPK + r] = (float)pi[r];
            }
            float mingap = 3.402823466e38f;
#pragma unroll
            for (int r = 0; r < TOPK; r++) {
                float gp = pv[r] - pv[r + 1];
                mingap = (gp < mingap) ? gp : mingap;
            }
            if (mingap < GAP_TAU) {
                int slot = atomicAdd(&g_risk_count, 1);
                g_risk_list[slot] = gt;
            }
        }
    }
}

// ---------------------------------------------------------------------------
// Kernel X1: rescue phase 1 — corrected h for flagged tokens.
// Same math as R12 rescue (single ascending-k fp32 FMA chain per hidden unit,
// + b1, leaky) but W1/x staged through SMEM so all global traffic is
// coalesced. Block b owns hidden units [b*16, b*16+16); processes flagged
// tokens in batches of 8. Writes corrected h into g_h[token] (router has
// already consumed g_h).
// ---------------------------------------------------------------------------
#define R1_UNITS 16
#define R1_TB    8
#define R1_PAD   2049
#define SMEM_R1  ((R1_UNITS + R1_TB) * R1_PAD * 4)   // 196704 bytes

__global__ __launch_bounds__(256, 1)
void rescue1_kernel(const float* __restrict__ X,
                    const float* __restrict__ W1,
                    const float* __restrict__ b1)
{
    extern __shared__ float sm[];
    float* W1s = sm;                        // [R1_UNITS][R1_PAD]
    float* xs  = sm + R1_UNITS * R1_PAD;    // [R1_TB][R1_PAD]

    const int tid = threadIdx.x;
    const int u0  = blockIdx.x * R1_UNITS;
    const int cnt = g_risk_count;
    if (cnt == 0) return;

    // load W1 slice once (coalesced)
    for (int idx = tid; idx < R1_UNITS * (D_IN / 4); idx += 256) {
        const int r  = idx >> 9;          // D_IN/4 = 512
        const int c4 = idx & 511;
        float4 v = *(const float4*)(W1 + (size_t)(u0 + r) * D_IN + c4 * 4);
        float* d = W1s + r * R1_PAD + c4 * 4;
        d[0] = v.x; d[1] = v.y; d[2] = v.z; d[3] = v.w;
    }

    for (int tb = 0; tb < cnt; tb += R1_TB) {
        __syncthreads();
        // stage x for this token batch (coalesced)
        for (int idx = tid; idx < R1_TB * (D_IN / 4); idx += 256) {
            const int t  = idx >> 9;
            const int c4 = idx & 511;
            if (tb + t < cnt) {
                const int tok = g_risk_list[tb + t];
                float4 v = *(const float4*)(X + (size_t)tok * D_IN + c4 * 4);
                float* d = xs + t * R1_PAD + c4 * 4;
                d[0] = v.x; d[1] = v.y; d[2] = v.z; d[3] = v.w;
            }
        }
        __syncthreads();

        if (tid < R1_TB * R1_UNITS) {
            const int t = tid >> 4;       // 0..7
            const int u = tid & 15;       // 0..15
            if (tb + t < cnt) {
                const float* xr = xs + t * R1_PAD;
                const float* wr = W1s + u * R1_PAD;
                float a = 0.0f;
#pragma unroll 8
                for (int k = 0; k < D_IN; k++)
                    a = fmaf(xr[k], wr[k], a);
                a += b1[u0 + u];
                a = (a >= 0.0f) ? a : 0.01f * a;
                const int tok = g_risk_list[tb + t];
                g_h[(size_t)tok * D_HID + u0 + u] = a;
            }
        }
    }
}

// ---------------------------------------------------------------------------
// Kernel X2: rescue phase 2 — logits + top-8 + softmax for flagged tokens.
// Same math as R12 rescue (single ascending-d fp32 chain per expert, acc
// carried across the two SMEM-staged W2 chunks), identical top-k/softmax.
// ---------------------------------------------------------------------------
#define R2_KC  512
#define R2_PAD 513
#define SMEM_R2 ((NEXP * R2_PAD + D_HID + NEXP) * 4)   // 135680 bytes

__global__ __launch_bounds__(256, 1)
void rescue2_kernel(const float* __restrict__ W2,
                    const float* __restrict__ b2,
                    float* __restrict__ out,
                    int write_indices)
{
    extern __shared__ float sm[];
    float* W2s = sm;                       // [NEXP][R2_PAD]
    float* hs  = sm + NEXP * R2_PAD;       // [D_HID]
    float* lg  = hs + D_HID;               // [NEXP]

    const int tid = threadIdx.x;
    const int cnt = g_risk_count;

    for (int it = blockIdx.x; it < cnt; it += gridDim.x) {
        const int t = g_risk_list[it];
        __syncthreads();
        // stage corrected h (coalesced)
        for (int idx = tid; idx < D_HID / 4; idx += 256) {
            float4 v = *(const float4*)(g_h + (size_t)t * D_HID + idx * 4);
            hs[idx * 4 + 0] = v.x; hs[idx * 4 + 1] = v.y;
            hs[idx * 4 + 2] = v.z; hs[idx * 4 + 3] = v.w;
        }

        float acc = 0.0f;
        for (int kc = 0; kc < D_HID; kc += R2_KC) {
            __syncthreads();
            // stage W2 chunk (coalesced)
            for (int idx = tid; idx < NEXP * (R2_KC / 4); idx += 256) {
                const int r  = idx >> 7;        // R2_KC/4 = 128
                const int c4 = idx & 127;
                float4 v = *(const float4*)(W2 + (size_t)r * D_HID + kc + c4 * 4);
                float* d = W2s + r * R2_PAD + c4 * 4;
                d[0] = v.x; d[1] = v.y; d[2] = v.z; d[3] = v.w;
            }
            __syncthreads();
            if (tid < NEXP) {
                const float* wr = W2s + tid * R2_PAD;
                const float* hr = hs + kc;
#pragma unroll 8
                for (int k = 0; k < R2_KC; k++)
                    acc = fmaf(hr[k], wr[k], acc);
            }
        }
        if (tid < NEXP) lg[tid] = acc + b2[tid];
        __syncthreads();

        // warp 0: top-8 + softmax, overwrite outputs (identical to R12)
        if (tid < 32) {
            const int lane = tid;
            const float NEG = -3.402823466e38f;
            float v0 = lg[lane];
            float v1 = lg[32 + lane];
            const int i0 = lane;
            const int i1 = lane + 32;

            float pv[TOPK];
            int   pi[TOPK];
#pragma unroll
            for (int r = 0; r < TOPK; r++) {
                float bv; int bi;
                if (v0 >= v1) { bv = v0; bi = i0; } else { bv = v1; bi = i1; }
#pragma unroll
                for (int off = 16; off >= 1; off >>= 1) {
                    float ov = __shfl_xor_sync(0xffffffffu, bv, off);
                    int   oi = __shfl_xor_sync(0xffffffffu, bi, off);
                    if (ov > bv || (ov == bv && oi < bi)) { bv = ov; bi = oi; }
                }
                pv[r] = bv; pi[r] = bi;
                if (bi == i0)       v0 = NEG;
                else if (bi == i1)  v1 = NEG;
            }

            if (lane == 0) {
                const float mx = pv[0];
                float e[TOPK], sum = 0.0f;
#pragma unroll
                for (int r = 0; r < TOPK; r++) { e[r] = expf(pv[r] - mx); sum += e[r]; }
                const float inv = 1.0f / sum;
#pragma unroll
                for (int r = 0; r < TOPK; r++)
                    out[(size_t)t * TOPK + r] = e[r] * inv;
                if (write_indices) {
#pragma unroll
                    for (int r = 0; r < TOPK; r++)
                        out[(size_t)TOKENS * TOPK + (size_t)t * TOPK + r] = (float)pi[r];
                }
            }
        }
    }
}

// ---------------------------------------------------------------------------
extern "C" void kernel_launch(void* const* d_in, const int* in_sizes, int n_in,
                              void* d_out, int out_size)
{
    const float* X  = (const float*)d_in[0];
    const float* W1 = (const float*)d_in[1];
    const float* b1 = (const float*)d_in[2];
    const float* W2 = (const float*)d_in[3];
    const float* b2 = (const float*)d_in[4];
    float* out = (float*)d_out;

    const int write_indices = (out_size >= 2 * TOKENS * TOPK) ? 1 : 0;

    cudaFuncSetAttribute(gemm1_mma_kernel,
                         cudaFuncAttributeMaxDynamicSharedMemorySize, SMEM_TOTAL_G);
    cudaFuncSetAttribute(rescue1_kernel,
                         cudaFuncAttributeMaxDynamicSharedMemorySize, SMEM_R1);
    cudaFuncSetAttribute(rescue2_kernel,
                         cudaFuncAttributeMaxDynamicSharedMemorySize, SMEM_R2);

    zero_kernel<<<1, 1>>>();
    split_kernel<<<4096, 256>>>(X,  (TOKENS * D_IN) / 4, 0);
    split_kernel<<<2048, 256>>>(W1, (D_HID * D_IN) / 4, 1);

    dim3 gg(D_HID / GN, TOKENS / GM);
    gemm1_mma_kernel<<<gg, 256, SMEM_TOTAL_G>>>(b1);

    router_kernel<<<TOKENS / TT, 256>>>(W2, b2, out, write_indices);

    rescue1_kernel<<<D_HID / R1_UNITS, 256, SMEM_R1>>>(X, W1, b1);
    rescue2_kernel<<<64, 256, SMEM_R2>>>(W2, b2, out, write_indices);
}

// round 15
// speedup vs baseline: 2.7503x; 1.0947x over previous
#include <cuda_runtime.h>
#include <cuda_fp16.h>
#include <math.h>
#include <stdint.h>

#define TOKENS  16384
#define D_IN    2048
#define D_HID   1024
#define NEXP    64
#define TOPK    8

// ---------------------------------------------------------------------------
// Scratch (__device__ globals: allowed)
// ---------------------------------------------------------------------------
__device__ float  g_h[(size_t)TOKENS * D_HID];        // fp32 h, rescue rows only
__device__ __half g_xh[(size_t)TOKENS * D_IN];
__device__ __half g_xl[(size_t)TOKENS * D_IN];
__device__ __half g_wh[(size_t)D_HID * D_IN];
__device__ __half g_wl[(size_t)D_HID * D_IN];
__device__ __half g_hh[(size_t)TOKENS * D_HID];       // fp16 split of h (high)
__device__ __half g_hl[(size_t)TOKENS * D_HID];       // fp16 split of h (low*2048)
__device__ __half g_w2h[(size_t)NEXP * D_HID];
__device__ __half g_w2l[(size_t)NEXP * D_HID];
__device__ int    g_risk_count;
__device__ int    g_risk_list[TOKENS];

// ---------------------------------------------------------------------------
// Helpers
// ---------------------------------------------------------------------------
__device__ __forceinline__ uint32_t smem_to_u32(const void* smem_ptr) {
    uint32_t addr;
    asm("{ .reg .u64 tmp; cvta.to.shared.u64 tmp, %1; cvt.u32.u64 %0, tmp; }"
        : "=r"(addr) : "l"(smem_ptr));
    return addr;
}

__device__ __forceinline__ void cp16(uint32_t s, const void* g) {
    asm volatile("cp.async.cg.shared.global [%0], [%1], 16;" :: "r"(s), "l"(g));
}
#define CP_COMMIT()  asm volatile("cp.async.commit_group;" ::: "memory")
#define CP_WAIT2()   asm volatile("cp.async.wait_group 2;" ::: "memory")
#define CP_WAIT1()   asm volatile("cp.async.wait_group 1;" ::: "memory")
#define CP_WAIT0()   asm volatile("cp.async.wait_group 0;" ::: "memory")

__device__ __forceinline__ void ldsm_x4(uint32_t* r, uint32_t addr) {
    asm volatile("ldmatrix.sync.aligned.m8n8.x4.shared.b16 {%0,%1,%2,%3}, [%4];"
        : "=r"(r[0]), "=r"(r[1]), "=r"(r[2]), "=r"(r[3]) : "r"(addr));
}
__device__ __forceinline__ void ldsm_x2(uint32_t* r, uint32_t addr) {
    asm volatile("ldmatrix.sync.aligned.m8n8.x2.shared.b16 {%0,%1}, [%2];"
        : "=r"(r[0]), "=r"(r[1]) : "r"(addr));
}

__device__ __forceinline__ void mma16816(float* c, const uint32_t* a, const uint32_t* b) {
    asm volatile(
        "mma.sync.aligned.m16n8k16.row.col.f32.f16.f16.f32 "
        "{%0,%1,%2,%3}, {%4,%5,%6,%7}, {%8,%9}, {%0,%1,%2,%3};"
        : "+f"(c[0]), "+f"(c[1]), "+f"(c[2]), "+f"(c[3])
        : "r"(a[0]), "r"(a[1]), "r"(a[2]), "r"(a[3]), "r"(b[0]), "r"(b[1]));
}

__device__ __forceinline__ uint32_t sw128(uint32_t off) {
    return off ^ ((off >> 3) & 0x70);
}

// ---------------------------------------------------------------------------
// Kernel Z: reset at-risk counter
// ---------------------------------------------------------------------------
__global__ void zero_kernel() { g_risk_count = 0; }

// ---------------------------------------------------------------------------
// Kernel S: fp16 2-way split. a = h + l/2048, l stored pre-scaled by 2048.
// which: 0 -> X, 1 -> W1, 2 -> W2
// ---------------------------------------------------------------------------
__global__ void split_kernel(const float* __restrict__ src, int n4, int which)
{
    __half *dh, *dl;
    if      (which == 0) { dh = g_xh;  dl = g_xl;  }
    else if (which == 1) { dh = g_wh;  dl = g_wl;  }
    else                 { dh = g_w2h; dl = g_w2l; }

    int i = blockIdx.x * blockDim.x + threadIdx.x;
    const int stride = gridDim.x * blockDim.x;
    for (; i < n4; i += stride) {
        float4 v = ((const float4*)src)[i];
        float a[4] = {v.x, v.y, v.z, v.w};
        __half h[4], l[4];
#pragma unroll
        for (int j = 0; j < 4; j++) {
            h[j] = __float2half(a[j]);
            float r = (a[j] - __half2float(h[j])) * 2048.0f;
            l[j] = __float2half(r);
        }
        __half2* ph = (__half2*)dh;
        __half2* pl = (__half2*)dl;
        ph[2*i]   = __half2(h[0], h[1]);
        ph[2*i+1] = __half2(h[2], h[3]);
        pl[2*i]   = __half2(l[0], l[1]);
        pl[2*i+1] = __half2(l[2], l[3]);
    }
}

// ---------------------------------------------------------------------------
// Kernel G: h = leaky(x @ W1^T + b1), mma.sync fp16 split GEMM (3 products)
// Mainloop byte-identical to R13. Epilogue now emits the fp16 2-way split of
// h (g_hh, g_hl) instead of fp32 g_h — same write bytes, feeds MMA router.
// ---------------------------------------------------------------------------
#define GM 128
#define GN 128
#define GK 64
#define NCHUNK (D_IN / GK)          // 32
#define TILE_B 16384                // 128 rows x 128 bytes (SW128)
#define NSTAGE 3
#define STAGE_B (4 * TILE_B)        // Ah Al Bh Bl = 64 KB
#define SMEM_CTRL 1024
#define SMEM_TOTAL_G (SMEM_CTRL + NSTAGE * STAGE_B)   // 197632

__global__ __launch_bounds__(256, 1)
void gemm1_mma_kernel(const float* __restrict__ b1)
{
    extern __shared__ char smem[];
    const uint32_t sb = smem_to_u32(smem);
    const int tid  = threadIdx.x;
    const int wid  = tid >> 5;
    const int lane = tid & 31;
    const int m0 = blockIdx.y * GM;
    const int n0 = blockIdx.x * GN;

    const int wm0 = (wid & 1) * 64;
    const int wn0 = (wid >> 1) * 32;

    size_t   goff[4];
    uint32_t soff[4];
#pragma unroll
    for (int p = 0; p < 4; p++) {
        int u = tid + p * 256;
        int row = u >> 3, c16 = u & 7;
        goff[p] = (size_t)row * D_IN + c16 * 8;
        soff[p] = sw128(row * 128 + c16 * 16);
    }

    const __half* Ab[2] = { g_xh + (size_t)m0 * D_IN, g_xl + (size_t)m0 * D_IN };
    const __half* Bb[2] = { g_wh + (size_t)n0 * D_IN, g_wl + (size_t)n0 * D_IN };

    auto load_chunk = [&](int chunk, int buf) {
        const int kt = chunk * GK;
        const uint32_t stg = sb + SMEM_CTRL + buf * STAGE_B;
#pragma unroll
        for (int t = 0; t < 4; t++) {
            const __half* base = (t < 2) ? Ab[t] : Bb[t - 2];
            const uint32_t sbase = stg + t * TILE_B;
#pragma unroll
            for (int p = 0; p < 4; p++)
                cp16(sbase + soff[p], base + goff[p] + kt);
        }
        CP_COMMIT();
    };

    const uint32_t a_row = wm0 + (lane & 15);
    const uint32_t a_kb  = (lane >> 4) * 16;
    const uint32_t b_row = wn0 + (lane & 7);
    const uint32_t b_kb  = ((lane >> 3) & 1) * 16;

    float acc0[4][4][4];
    float acc1[4][4][4];
#pragma unroll
    for (int mi = 0; mi < 4; mi++)
#pragma unroll
        for (int ni = 0; ni < 4; ni++)
#pragma unroll
            for (int e = 0; e < 4; e++) { acc0[mi][ni][e] = 0.0f; acc1[mi][ni][e] = 0.0f; }

    load_chunk(0, 0);
    load_chunk(1, 1);
    load_chunk(2, 2);

    for (int i = 0; i < NCHUNK; i++) {
        if (i + 3 <= NCHUNK)      CP_WAIT2();
        else if (i + 2 <= NCHUNK) CP_WAIT1();
        else                      CP_WAIT0();
        __syncthreads();

        const uint32_t stg = sb + SMEM_CTRL + (i % NSTAGE) * STAGE_B;
        const uint32_t ah = stg;
        const uint32_t al = stg + TILE_B;
        const uint32_t bh = stg + 2 * TILE_B;
        const uint32_t bl = stg + 3 * TILE_B;

#pragma unroll
        for (int ks = 0; ks < 4; ks++) {
            uint32_t afh[4][4], afl[4][4];
#pragma unroll
            for (int mi = 0; mi < 4; mi++) {
                uint32_t off = (a_row + mi * 16) * 128 + ks * 32 + a_kb;
                uint32_t sw  = sw128(off);
                ldsm_x4(afh[mi], ah + sw);
                ldsm_x4(afl[mi], al + sw);
            }
            uint32_t bfh[4][2], bfl[4][2];
#pragma unroll
            for (int ni = 0; ni < 4; ni++) {
                uint32_t off = (b_row + ni * 8) * 128 + ks * 32 + b_kb;
                uint32_t sw  = sw128(off);
                ldsm_x2(bfh[ni], bh + sw);
                ldsm_x2(bfl[ni], bl + sw);
            }
#pragma unroll
            for (int mi = 0; mi < 4; mi++)
#pragma unroll
                for (int ni = 0; ni < 4; ni++)
                    mma16816(acc0[mi][ni], afh[mi], bfh[ni]);
#pragma unroll
            for (int mi = 0; mi < 4; mi++)
#pragma unroll
                for (int ni = 0; ni < 4; ni++)
                    mma16816(acc1[mi][ni], afh[mi], bfl[ni]);
#pragma unroll
            for (int mi = 0; mi < 4; mi++)
#pragma unroll
                for (int ni = 0; ni < 4; ni++)
                    mma16816(acc1[mi][ni], afl[mi], bfh[ni]);
        }
        __syncthreads();
        if (i + 3 < NCHUNK) load_chunk(i + 3, (i + 3) % NSTAGE);
    }

    const float CS = 1.0f / 2048.0f;
    float2 bv[4];
#pragma unroll
    for (int ni = 0; ni < 4; ni++) {
        int col = n0 + wn0 + ni * 8 + (lane & 3) * 2;
        bv[ni] = make_float2(b1[col], b1[col + 1]);
    }

#pragma unroll
    for (int mi = 0; mi < 4; mi++) {
        const int r0 = m0 + wm0 + mi * 16 + (lane >> 2);
#pragma unroll
        for (int ni = 0; ni < 4; ni++) {
            const int col = n0 + wn0 + ni * 8 + (lane & 3) * 2;
            float t0 = acc0[mi][ni][0] + CS * acc1[mi][ni][0] + bv[ni].x;
            float t1 = acc0[mi][ni][1] + CS * acc1[mi][ni][1] + bv[ni].y;
            float t2 = acc0[mi][ni][2] + CS * acc1[mi][ni][2] + bv[ni].x;
            float t3 = acc0[mi][ni][3] + CS * acc1[mi][ni][3] + bv[ni].y;
            t0 = (t0 >= 0.f) ? t0 : 0.01f * t0;
            t1 = (t1 >= 0.f) ? t1 : 0.01f * t1;
            t2 = (t2 >= 0.f) ? t2 : 0.01f * t2;
            t3 = (t3 >= 0.f) ? t3 : 0.01f * t3;

            // fp16 2-way split of h (same scheme as inputs)
            __half h0 = __float2half(t0), h1 = __float2half(t1);
            __half h2 = __float2half(t2), h3 = __float2half(t3);
            __half l0 = __float2half((t0 - __half2float(h0)) * 2048.0f);
            __half l1 = __float2half((t1 - __half2float(h1)) * 2048.0f);
            __half l2 = __float2half((t2 - __half2float(h2)) * 2048.0f);
            __half l3 = __float2half((t3 - __half2float(h3)) * 2048.0f);

            const size_t o0 = (size_t)r0 * D_HID + col;
            const size_t o1 = (size_t)(r0 + 8) * D_HID + col;
            *(__half2*)(g_hh + o0) = __half2(h0, h1);
            *(__half2*)(g_hh + o1) = __half2(h2, h3);
            *(__half2*)(g_hl + o0) = __half2(l0, l1);
            *(__half2*)(g_hl + o1) = __half2(l2, l3);
        }
    }
}

// ---------------------------------------------------------------------------
// Kernel R: MMA router. logits = h @ W2^T + b2 via 3-product fp16 split MMA
// (CTA = 128 tokens x 64 experts, K=1024, 3-stage cp.async). Then top-9,
// softmax over top-8, flag tokens with min gap < GAP_TAU.
// ---------------------------------------------------------------------------
#define RT 128
#define RBK 64
#define R_TILE_A 16384              // 128 rows x 128B
#define R_TILE_B 8192               // 64 rows x 128B
#define R_STAGE (2 * R_TILE_A + 2 * R_TILE_B)   // 49152
#define R_NSTAGE 3
#define R_NCHUNK (D_HID / RBK)      // 16
#define LSTR 68
#define SMEM_R (R_NSTAGE * R_STAGE) // 147456 (logits overlay after mainloop)
#define GAP_TAU 2e-4f

__global__ __launch_bounds__(256, 1)
void router_mma_kernel(const float* __restrict__ b2,
                       float* __restrict__ out,
                       int write_indices)
{
    extern __shared__ char smem[];
    const uint32_t sb = smem_to_u32(smem);
    float* Lg = (float*)smem;     // [RT][LSTR] overlay after mainloop

    const int tid  = threadIdx.x;
    const int wid  = tid >> 5;
    const int lane = tid & 31;
    const int t0   = blockIdx.x * RT;

    const int wm0 = (wid & 1) * 64;     // token half
    const int wn0 = (wid >> 1) * 16;    // expert quarter

    // loader geometry
    // A parts: 1024 16B-units each (4/thread); B parts: 512 units (2/thread)
    size_t   gaoff[4];
    uint32_t saoff[4];
#pragma unroll
    for (int p = 0; p < 4; p++) {
        int u = tid + p * 256;
        int row = u >> 3, c16 = u & 7;
        gaoff[p] = (size_t)row * D_HID + c16 * 8;
        saoff[p] = sw128(row * 128 + c16 * 16);
    }
    size_t   gboff[2];
    uint32_t sboff[2];
#pragma unroll
    for (int p = 0; p < 2; p++) {
        int u = tid + p * 256;
        int row = u >> 3, c16 = u & 7;
        gboff[p] = (size_t)row * D_HID + c16 * 8;
        sboff[p] = sw128(row * 128 + c16 * 16);
    }

    const __half* Ahg = g_hh + (size_t)t0 * D_HID;
    const __half* Alg = g_hl + (size_t)t0 * D_HID;

    auto load_chunk = [&](int chunk, int buf) {
        const int kt = chunk * RBK;
        const uint32_t stg = sb + buf * R_STAGE;
#pragma unroll
        for (int p = 0; p < 4; p++) {
            cp16(stg + saoff[p],            Ahg + gaoff[p] + kt);
            cp16(stg + R_TILE_A + saoff[p], Alg + gaoff[p] + kt);
        }
#pragma unroll
        for (int p = 0; p < 2; p++) {
            cp16(stg + 2 * R_TILE_A + sboff[p],            g_w2h + gboff[p] + kt);
            cp16(stg + 2 * R_TILE_A + R_TILE_B + sboff[p], g_w2l + gboff[p] + kt);
        }
        CP_COMMIT();
    };

    const uint32_t a_row = wm0 + (lane & 15);
    const uint32_t a_kb  = (lane >> 4) * 16;
    const uint32_t b_row = wn0 + (lane & 7);
    const uint32_t b_kb  = ((lane >> 3) & 1) * 16;

    float acc0[4][2][4];
    float acc1[4][2][4];
#pragma unroll
    for (int mi = 0; mi < 4; mi++)
#pragma unroll
        for (int ni = 0; ni < 2; ni++)
#pragma unroll
            for (int e = 0; e < 4; e++) { acc0[mi][ni][e] = 0.0f; acc1[mi][ni][e] = 0.0f; }

    load_chunk(0, 0);
    load_chunk(1, 1);
    load_chunk(2, 2);

    for (int i = 0; i < R_NCHUNK; i++) {
        if (i + 3 <= R_NCHUNK)      CP_WAIT2();
        else if (i + 2 <= R_NCHUNK) CP_WAIT1();
        else                        CP_WAIT0();
        __syncthreads();

        const uint32_t stg = sb + (i % R_NSTAGE) * R_STAGE;
        const uint32_t ah = stg;
        const uint32_t al = stg + R_TILE_A;
        const uint32_t bh = stg + 2 * R_TILE_A;
        const uint32_t bl = stg + 2 * R_TILE_A + R_TILE_B;

#pragma unroll
        for (int ks = 0; ks < 4; ks++) {
            uint32_t afh[4][4], afl[4][4];
#pragma unroll
            for (int mi = 0; mi < 4; mi++) {
                uint32_t off = (a_row + mi * 16) * 128 + ks * 32 + a_kb;
                uint32_t sw  = sw128(off);
                ldsm_x4(afh[mi], ah + sw);
                ldsm_x4(afl[mi], al + sw);
            }
            uint32_t bfh[2][2], bfl[2][2];
#pragma unroll
            for (int ni = 0; ni < 2; ni++) {
                uint32_t off = (b_row + ni * 8) * 128 + ks * 32 + b_kb;
                uint32_t sw  = sw128(off);
                ldsm_x2(bfh[ni], bh + sw);
                ldsm_x2(bfl[ni], bl + sw);
            }
#pragma unroll
            for (int mi = 0; mi < 4; mi++)
#pragma unroll
                for (int ni = 0; ni < 2; ni++)
                    mma16816(acc0[mi][ni], afh[mi], bfh[ni]);
#pragma unroll
            for (int mi = 0; mi < 4; mi++)
#pragma unroll
                for (int ni = 0; ni < 2; ni++)
                    mma16816(acc1[mi][ni], afh[mi], bfl[ni]);
#pragma unroll
            for (int mi = 0; mi < 4; mi++)
#pragma unroll
                for (int ni = 0; ni < 2; ni++)
                    mma16816(acc1[mi][ni], afl[mi], bfh[ni]);
        }
        __syncthreads();
        if (i + 3 < R_NCHUNK) load_chunk(i + 3, (i + 3) % R_NSTAGE);
    }

    // logits -> smem (overlay on stage smem; all reads done + sync above)
    const float CS = 1.0f / 2048.0f;
    float2 bv[2];
#pragma unroll
    for (int ni = 0; ni < 2; ni++) {
        int col = wn0 + ni * 8 + (lane & 3) * 2;
        bv[ni] = make_float2(b2[col], b2[col + 1]);
    }
#pragma unroll
    for (int mi = 0; mi < 4; mi++) {
        const int r0 = wm0 + mi * 16 + (lane >> 2);
#pragma unroll
        for (int ni = 0; ni < 2; ni++) {
            const int col = wn0 + ni * 8 + (lane & 3) * 2;
            float v0 = acc0[mi][ni][0] + CS * acc1[mi][ni][0] + bv[ni].x;
            float v1 = acc0[mi][ni][1] + CS * acc1[mi][ni][1] + bv[ni].y;
            float v2 = acc0[mi][ni][2] + CS * acc1[mi][ni][2] + bv[ni].x;
            float v3 = acc0[mi][ni][3] + CS * acc1[mi][ni][3] + bv[ni].y;
            *(float2*)&Lg[r0 * LSTR + col]       = make_float2(v0, v1);
            *(float2*)&Lg[(r0 + 8) * LSTR + col] = make_float2(v2, v3);
        }
    }
    __syncthreads();

    // top-9 + softmax + flag: warp w handles 16 tokens
    const int warp = wid;
    const float NEG = -3.402823466e38f;

    for (int s = 0; s < 16; s++) {
        const int lt = warp * 16 + s;
        float v0 = Lg[lt * LSTR + lane];
        float v1 = Lg[lt * LSTR + 32 + lane];
        const int i0 = lane;
        const int i1 = lane + 32;

        float pv[TOPK + 1];
        int   pi[TOPK + 1];
#pragma unroll
        for (int r = 0; r < TOPK + 1; r++) {
            float bvv; int bi;
            if (v0 >= v1) { bvv = v0; bi = i0; } else { bvv = v1; bi = i1; }
#pragma unroll
            for (int off = 16; off >= 1; off >>= 1) {
                float ov = __shfl_xor_sync(0xffffffffu, bvv, off);
                int   oi = __shfl_xor_sync(0xffffffffu, bi, off);
                if (ov > bvv || (ov == bvv && oi < bi)) { bvv = ov; bi = oi; }
            }
            pv[r] = bvv; pi[r] = bi;
            if (bi == i0)       v0 = NEG;
            else if (bi == i1)  v1 = NEG;
        }

        if (lane == 0) {
            const int gt = t0 + lt;
            const float mx = pv[0];
            float e[TOPK], sum = 0.0f;
#pragma unroll
            for (int r = 0; r < TOPK; r++) { e[r] = expf(pv[r] - mx); sum += e[r]; }
            const float inv = 1.0f / sum;
#pragma unroll
            for (int r = 0; r < TOPK; r++)
                out[(size_t)gt * TOPK + r] = e[r] * inv;
            if (write_indices) {
#pragma unroll
                for (int r = 0; r < TOPK; r++)
                    out[(size_t)TOKENS * TOPK + (size_t)gt * TOPK + r] = (float)pi[r];
            }
            float mingap = 3.402823466e38f;
#pragma unroll
            for (int r = 0; r < TOPK; r++) {
                float gp = pv[r] - pv[r + 1];
                mingap = (gp < mingap) ? gp : mingap;
            }
            if (mingap < GAP_TAU) {
                int slot = atomicAdd(&g_risk_count, 1);
                g_risk_list[slot] = gt;
            }
        }
    }
}

// ---------------------------------------------------------------------------
// Kernel X1: rescue phase 1 — corrected fp32 h for flagged tokens
// (ascending-k single fp32 FMA chain; W1/x SMEM-staged, coalesced).
// TB=16 halves the number of serial-chain batches vs R13.
// ---------------------------------------------------------------------------
#define R1_UNITS 8
#define R1_TB    16
#define R1_PAD   2049
#define SMEM_R1  ((R1_UNITS + R1_TB) * R1_PAD * 4)   // 196704

__global__ __launch_bounds__(256, 1)
void rescue1_kernel(const float* __restrict__ X,
                    const float* __restrict__ W1,
                    const float* __restrict__ b1)
{
    extern __shared__ float sm[];
    float* W1s = sm;                        // [R1_UNITS][R1_PAD]
    float* xs  = sm + R1_UNITS * R1_PAD;    // [R1_TB][R1_PAD]

    const int tid = threadIdx.x;
    const int u0  = blockIdx.x * R1_UNITS;
    const int cnt = g_risk_count;
    if (cnt == 0) return;

    for (int idx = tid; idx < R1_UNITS * (D_IN / 4); idx += 256) {
        const int r  = idx >> 9;
        const int c4 = idx & 511;
        float4 v = *(const float4*)(W1 + (size_t)(u0 + r) * D_IN + c4 * 4);
        float* d = W1s + r * R1_PAD + c4 * 4;
        d[0] = v.x; d[1] = v.y; d[2] = v.z; d[3] = v.w;
    }

    for (int tb = 0; tb < cnt; tb += R1_TB) {
        __syncthreads();
        for (int idx = tid; idx < R1_TB * (D_IN / 4); idx += 256) {
            const int t  = idx >> 9;
            const int c4 = idx & 511;
            if (tb + t < cnt) {
                const int tok = g_risk_list[tb + t];
                float4 v = *(const float4*)(X + (size_t)tok * D_IN + c4 * 4);
                float* d = xs + t * R1_PAD + c4 * 4;
                d[0] = v.x; d[1] = v.y; d[2] = v.z; d[3] = v.w;
            }
        }
        __syncthreads();

        if (tid < R1_TB * R1_UNITS) {
            const int t = tid >> 3;       // 0..15
            const int u = tid & 7;        // 0..7
            if (tb + t < cnt) {
                const float* xr = xs + t * R1_PAD;
                const float* wr = W1s + u * R1_PAD;
                float a = 0.0f;
#pragma unroll 8
                for (int k = 0; k < D_IN; k++)
                    a = fmaf(xr[k], wr[k], a);
                a += b1[u0 + u];
                a = (a >= 0.0f) ? a : 0.01f * a;
                const int tok = g_risk_list[tb + t];
                g_h[(size_t)tok * D_HID + u0 + u] = a;
            }
        }
    }
}

// ---------------------------------------------------------------------------
// Kernel X2: rescue phase 2 — logits + top-8 + softmax for flagged tokens
// (ascending-d fp32 chain carried across SMEM-staged W2 chunks).
// ---------------------------------------------------------------------------
#define R2_KC  512
#define R2_PAD 513
#define SMEM_R2 ((NEXP * R2_PAD + D_HID + NEXP) * 4)   // 135680

__global__ __launch_bounds__(256, 1)
void rescue2_kernel(const float* __restrict__ W2,
                    const float* __restrict__ b2,
                    float* __restrict__ out,
                    int write_indices)
{
    extern __shared__ float sm[];
    float* W2s = sm;
    float* hs  = sm + NEXP * R2_PAD;
    float* lg  = hs + D_HID;

    const int tid = threadIdx.x;
    const int cnt = g_risk_count;

    for (int it = blockIdx.x; it < cnt; it += gridDim.x) {
        const int t = g_risk_list[it];
        __syncthreads();
        for (int idx = tid; idx < D_HID / 4; idx += 256) {
            float4 v = *(const float4*)(g_h + (size_t)t * D_HID + idx * 4);
            hs[idx * 4 + 0] = v.x; hs[idx * 4 + 1] = v.y;
            hs[idx * 4 + 2] = v.z; hs[idx * 4 + 3] = v.w;
        }

        float acc = 0.0f;
        for (int kc = 0; kc < D_HID; kc += R2_KC) {
            __syncthreads();
            for (int idx = tid; idx < NEXP * (R2_KC / 4); idx += 256) {
                const int r  = idx >> 7;
                const int c4 = idx & 127;
                float4 v = *(const float4*)(W2 + (size_t)r * D_HID + kc + c4 * 4);
                float* d = W2s + r * R2_PAD + c4 * 4;
                d[0] = v.x; d[1] = v.y; d[2] = v.z; d[3] = v.w;
            }
            __syncthreads();
            if (tid < NEXP) {
                const float* wr = W2s + tid * R2_PAD;
                const float* hr = hs + kc;
#pragma unroll 8
                for (int k = 0; k < R2_KC; k++)
                    acc = fmaf(hr[k], wr[k], acc);
            }
        }
        if (tid < NEXP) lg[tid] = acc + b2[tid];
        __syncthreads();

        if (tid < 32) {
            const int lane = tid;
            const float NEG = -3.402823466e38f;
            float v0 = lg[lane];
            float v1 = lg[32 + lane];
            const int i0 = lane;
            const int i1 = lane + 32;

            float pv[TOPK];
            int   pi[TOPK];
#pragma unroll
            for (int r = 0; r < TOPK; r++) {
                float bv; int bi;
                if (v0 >= v1) { bv = v0; bi = i0; } else { bv = v1; bi = i1; }
#pragma unroll
                for (int off = 16; off >= 1; off >>= 1) {
                    float ov = __shfl_xor_sync(0xffffffffu, bv, off);
                    int   oi = __shfl_xor_sync(0xffffffffu, bi, off);
                    if (ov > bv || (ov == bv && oi < bi)) { bv = ov; bi = oi; }
                }
                pv[r] = bv; pi[r] = bi;
                if (bi == i0)       v0 = NEG;
                else if (bi == i1)  v1 = NEG;
            }

            if (lane == 0) {
                const float mx = pv[0];
                float e[TOPK], sum = 0.0f;
#pragma unroll
                for (int r = 0; r < TOPK; r++) { e[r] = expf(pv[r] - mx); sum += e[r]; }
                const float inv = 1.0f / sum;
#pragma unroll
                for (int r = 0; r < TOPK; r++)
                    out[(size_t)t * TOPK + r] = e[r] * inv;
                if (write_indices) {
#pragma unroll
                    for (int r = 0; r < TOPK; r++)
                        out[(size_t)TOKENS * TOPK + (size_t)t * TOPK + r] = (float)pi[r];
                }
            }
        }
    }
}

// ---------------------------------------------------------------------------
extern "C" void kernel_launch(void* const* d_in, const int* in_sizes, int n_in,
                              void* d_out, int out_size)
{
    const float* X  = (const float*)d_in[0];
    const float* W1 = (const float*)d_in[1];
    const float* b1 = (const float*)d_in[2];
    const float* W2 = (const float*)d_in[3];
    const float* b2 = (const float*)d_in[4];
    float* out = (float*)d_out;

    const int write_indices = (out_size >= 2 * TOKENS * TOPK) ? 1 : 0;

    cudaFuncSetAttribute(gemm1_mma_kernel,
                         cudaFuncAttributeMaxDynamicSharedMemorySize, SMEM_TOTAL_G);
    cudaFuncSetAttribute(router_mma_kernel,
                         cudaFuncAttributeMaxDynamicSharedMemorySize, SMEM_R);
    cudaFuncSetAttribute(rescue1_kernel,
                         cudaFuncAttributeMaxDynamicSharedMemorySize, SMEM_R1);
    cudaFuncSetAttribute(rescue2_kernel,
                         cudaFuncAttributeMaxDynamicSharedMemorySize, SMEM_R2);

    zero_kernel<<<1, 1>>>();
    split_kernel<<<4096, 256>>>(X,  (TOKENS * D_IN) / 4, 0);
    split_kernel<<<2048, 256>>>(W1, (D_HID * D_IN) / 4, 1);
    split_kernel<<<64, 256>>>(W2,   (NEXP * D_HID) / 4, 2);

    dim3 gg(D_HID / GN, TOKENS / GM);
    gemm1_mma_kernel<<<gg, 256, SMEM_TOTAL_G>>>(b1);

    router_mma_kernel<<<TOKENS / RT, 256, SMEM_R>>>(b2, out, write_indices);

    rescue1_kernel<<<D_HID / R1_UNITS, 256, SMEM_R1>>>(X, W1, b1);
    rescue2_kernel<<<64, 256, SMEM_R2>>>(W2, b2, out, write_indices);
}